// round 13
// baseline (speedup 1.0000x reference)
#include <cuda_runtime.h>
#include <cuda_bf16.h>
#include <cstdint>

#define N_ROWS  32768
#define D_DIM   512
#define K_CODES 8192
#define CAP     64
// Worst-case bf16 screening error bound: 2 * 2^-8 = 7.8e-3. EPS must exceed it.
#define EPS_MARGIN 1.25e-2f

// ---------------------------------------------------------------------------
// Device scratch
// ---------------------------------------------------------------------------
__device__ float          g_zn[N_ROWS  * D_DIM];   // 64 MB normalized z (fp32)
__device__ float          g_cn[K_CODES * D_DIM];   // 16 MB normalized codebook (fp32)
__device__ __nv_bfloat16  g_zb[N_ROWS  * D_DIM];   // 32 MB bf16 zn
__device__ __nv_bfloat16  g_cb[K_CODES * D_DIM];   //  8 MB bf16 cn
__device__ int            g_cand[N_ROWS][CAP];
__device__ int            g_candcnt[N_ROWS];
__device__ uint32_t       g_rowmax[N_ROWS];        // global running max (mono bits)
__device__ float          g_loss;

// ---------------------------------------------------------------------------
// Helpers
// ---------------------------------------------------------------------------
__device__ __forceinline__ uint32_t smem_u32(const void* p) {
    uint32_t a;
    asm("{ .reg .u64 t; cvta.to.shared.u64 t, %1; cvt.u32.u64 %0, t; }"
        : "=r"(a) : "l"(p));
    return a;
}
#define SWZ(o) ((o) ^ (((o) >> 3) & 0x70))

__device__ __forceinline__ void cp_async16(uint32_t dst, const void* src) {
    asm volatile("cp.async.cg.shared.global [%0], [%1], 16;"
                 :: "r"(dst), "l"(src) : "memory");
}
#define CP_COMMIT() asm volatile("cp.async.commit_group;" ::: "memory")
#define CP_WAIT1()  asm volatile("cp.async.wait_group 1;" ::: "memory")

__device__ __forceinline__ void ldsm_x4(uint32_t* r, uint32_t addr) {
    asm volatile("ldmatrix.sync.aligned.m8n8.x4.shared.b16 {%0,%1,%2,%3}, [%4];"
                 : "=r"(r[0]), "=r"(r[1]), "=r"(r[2]), "=r"(r[3]) : "r"(addr));
}
__device__ __forceinline__ void mma_bf16(float* c, const uint32_t* a,
                                         uint32_t b0, uint32_t b1) {
    asm volatile(
        "mma.sync.aligned.m16n8k16.row.col.f32.bf16.bf16.f32 "
        "{%0,%1,%2,%3}, {%4,%5,%6,%7}, {%8,%9}, {%0,%1,%2,%3};"
        : "+f"(c[0]), "+f"(c[1]), "+f"(c[2]), "+f"(c[3])
        : "r"(a[0]), "r"(a[1]), "r"(a[2]), "r"(a[3]), "r"(b0), "r"(b1));
}

// monotone float <-> uint (order-preserving)
__device__ __forceinline__ uint32_t mono(float v) {
    uint32_t u = __float_as_uint(v);
    return (u & 0x80000000u) ? ~u : (u | 0x80000000u);
}
__device__ __forceinline__ float unmono(uint32_t u) {
    return __uint_as_float((u & 0x80000000u) ? (u & 0x7fffffffu) : ~u);
}
__device__ __forceinline__ unsigned long long pack_key(float v, int col) {
    return ((unsigned long long)mono(v) << 32) | (unsigned)(~col);
}

// Sequential-order exact fp32 dot (bit-identical to the R1 kernel order that
// matched the reference argmax on every row).
__device__ __forceinline__ float dot_seq(const float* __restrict__ a,
                                         const float* __restrict__ b) {
    float s = 0.0f;
    #pragma unroll 16
    for (int q = 0; q < D_DIM / 4; ++q) {
        float4 av = ((const float4*)a)[q];
        float4 bv = ((const float4*)b)[q];
        s = fmaf(av.x, bv.x, s);
        s = fmaf(av.y, bv.y, s);
        s = fmaf(av.z, bv.z, s);
        s = fmaf(av.w, bv.w, s);
    }
    return s;
}

// ---------------------------------------------------------------------------
// Fused row L2-normalize: blocks [0, N_ROWS) handle z (+ per-row state init),
// blocks [N_ROWS, N_ROWS + K_CODES) handle the codebook.
// ---------------------------------------------------------------------------
__global__ void normalize_all(const float* __restrict__ z,
                              const float* __restrict__ codebook) {
    const bool is_z = blockIdx.x < N_ROWS;
    const int row = is_z ? blockIdx.x : (blockIdx.x - N_ROWS);
    const float* in = is_z ? z : codebook;
    float* out_f = is_z ? g_zn : g_cn;
    __nv_bfloat16* out_b = is_z ? g_zb : g_cb;

    if (is_z && threadIdx.x == 0) {
        g_candcnt[row] = 0;
        g_rowmax[row] = 0u;                 // mono(-inf)
        if (row == 0) g_loss = 0.0f;
    }
    float4 v = ((const float4*)(in + (size_t)row * D_DIM))[threadIdx.x];
    float ss = v.x * v.x + v.y * v.y + v.z * v.z + v.w * v.w;
    #pragma unroll
    for (int o = 16; o; o >>= 1) ss += __shfl_xor_sync(0xffffffffu, ss, o);
    __shared__ float ws[4];
    if ((threadIdx.x & 31) == 0) ws[threadIdx.x >> 5] = ss;
    __syncthreads();
    float inv = 1.0f / fmaxf(sqrtf(ws[0] + ws[1] + ws[2] + ws[3]), 1e-12f);
    float4 o4 = make_float4(v.x * inv, v.y * inv, v.z * inv, v.w * inv);
    ((float4*)(out_f + (size_t)row * D_DIM))[threadIdx.x] = o4;
    __nv_bfloat162 b0 = __floats2bfloat162_rn(o4.x, o4.y);
    __nv_bfloat162 b1 = __floats2bfloat162_rn(o4.z, o4.w);
    ((uint2*)(out_b + (size_t)row * D_DIM))[threadIdx.x] =
        make_uint2(*(uint32_t*)&b0, *(uint32_t*)&b1);
}

// ---------------------------------------------------------------------------
// HMMA bf16 screening GEMM + prefix-max candidate collection.
// Grid (4, 256): blockIdx.y = 128-row tile, blockIdx.x = 2048-col quarter.
// ---------------------------------------------------------------------------
#define SMEM_A    0           // 8 chunks * 16384 = 131072
#define SMEM_B    131072      // 3 stages * 32768 = 98304
#define SMEM_RMAX 229376      // 128 * 4 = 512
#define SMEM_TOT  229888

__device__ __forceinline__ void prefetch_b(uint32_t sb, int colQ, int cg, int tid) {
    const int nt = cg >> 3, c = cg & 7;
    const uint32_t dstb = sb + SMEM_B + (cg % 3) * 32768;
    #pragma unroll
    for (int it = 0; it < 8; ++it) {
        int u = tid + it * 256;             // 0..2047 16B units
        int r = u >> 3, cu = u & 7;         // code row 0..255
        cp_async16(dstb + SWZ(r * 128 + cu * 16),
                   &g_cb[(size_t)(colQ + nt * 256 + r) * D_DIM + c * 64 + cu * 8]);
    }
}

__global__ __launch_bounds__(256, 1) void gemm_screen() {
    extern __shared__ char smem[];
    const uint32_t sb = smem_u32(smem);
    const int tid = threadIdx.x;
    const int lane = tid & 31;
    const int wid = tid >> 5;
    const int warpM = wid >> 2;      // 0..1  (64 rows each)
    const int warpN = wid & 3;       // 0..3  (64 cols each)
    const int rowBase = blockIdx.y * 128;
    const int colQ = blockIdx.x * 2048;
    uint32_t* srunmax = (uint32_t*)(smem + SMEM_RMAX);

    if (tid < 128) srunmax[tid] = 0u;   // mono(-inf)

    // Group 0: resident A (128 rows x 512 bf16, chunk-major, swizzled)
    #pragma unroll
    for (int it = 0; it < 32; ++it) {
        int u = tid + it * 256;             // 0..8191 16B-units
        int c  = u >> 10;
        int r  = (u >> 3) & 127;
        int cu = u & 7;
        cp_async16(sb + SMEM_A + c * 16384 + SWZ(r * 128 + cu * 16),
                   &g_zb[(size_t)(rowBase + r) * D_DIM + c * 64 + cu * 8]);
    }
    CP_COMMIT();

    prefetch_b(sb, colQ, 0, tid); CP_COMMIT();
    prefetch_b(sb, colQ, 1, tid); CP_COMMIT();

    float acc[4][8][4];                 // 64 rows x 64 cols per warp

    const int ra = warpM * 64 + (lane & 15);
    const int ca = (lane >> 4);
    const int nb = warpN * 64 + (lane & 7) + ((lane >> 4) << 3);
    const int cb = (lane >> 3) & 1;

    for (int cg = 0; cg < 64; ++cg) {   // 8 tiles * 8 chunks
        const int nt = cg >> 3;
        const int c  = cg & 7;

        CP_WAIT1();
        __syncthreads();
        // safe: slot (cg+2)%3 == (cg-1)%3; barrier above post-dates chunk
        // cg-1 compute on all warps.
        if (cg + 2 < 64) prefetch_b(sb, colQ, cg + 2, tid);
        CP_COMMIT();

        if (c == 0) {
            #pragma unroll
            for (int m = 0; m < 4; ++m)
                #pragma unroll
                for (int j = 0; j < 8; ++j)
                    #pragma unroll
                    for (int e = 0; e < 4; ++e) acc[m][j][e] = 0.0f;
        }

        const uint32_t Ab = sb + SMEM_A + c * 16384;
        const uint32_t Bb = sb + SMEM_B + (cg % 3) * 32768;

        #pragma unroll
        for (int s = 0; s < 4; ++s) {   // 4 k16-steps within the 64-k chunk
            uint32_t a[4][4], b4[4][4];
            #pragma unroll
            for (int m = 0; m < 4; ++m)
                ldsm_x4(a[m], Ab + SWZ((ra + m * 16) * 128 + (s * 2 + ca) * 16));
            #pragma unroll
            for (int q = 0; q < 4; ++q)
                ldsm_x4(b4[q], Bb + SWZ((nb + q * 16) * 128 + (s * 2 + cb) * 16));
            #pragma unroll
            for (int m = 0; m < 4; ++m)
                #pragma unroll
                for (int j = 0; j < 8; ++j)
                    mma_bf16(acc[m][j], a[m],
                             b4[j >> 1][(j & 1) * 2], b4[j >> 1][(j & 1) * 2 + 1]);
        }

        if (c == 7) {
            // ---- epilogue for tile nt ----
            const int g = lane >> 2, tg = lane & 3;
            #pragma unroll
            for (int m = 0; m < 4; ++m)
                #pragma unroll
                for (int h = 0; h < 2; ++h) {
                    int row = warpM * 64 + m * 16 + h * 8 + g;
                    float mx = -1e30f;
                    #pragma unroll
                    for (int j = 0; j < 8; ++j)
                        mx = fmaxf(mx, fmaxf(acc[m][j][h * 2], acc[m][j][h * 2 + 1]));
                    mx = fmaxf(mx, __shfl_xor_sync(0xffffffffu, mx, 1));
                    mx = fmaxf(mx, __shfl_xor_sync(0xffffffffu, mx, 2));
                    if (tg == 0) atomicMax(&srunmax[row], mono(mx));
                }
            __syncthreads();
            // couple with global running max (publish ours, adopt best known)
            if (tid < 128) {
                uint32_t lm = srunmax[tid];
                uint32_t old = atomicMax(&g_rowmax[rowBase + tid], lm);
                if (old > lm) srunmax[tid] = old;
            }
            __syncthreads();
            #pragma unroll
            for (int m = 0; m < 4; ++m)
                #pragma unroll
                for (int h = 0; h < 2; ++h) {
                    int row = warpM * 64 + m * 16 + h * 8 + g;
                    float thr = unmono(srunmax[row]) - EPS_MARGIN;
                    #pragma unroll
                    for (int j = 0; j < 8; ++j)
                        #pragma unroll
                        for (int e = 0; e < 2; ++e) {
                            float v = acc[m][j][h * 2 + e];
                            if (v >= thr) {
                                int col = colQ + nt * 256 + warpN * 64 + j * 8 + 2 * tg + e;
                                int pos = atomicAdd(&g_candcnt[rowBase + row], 1);
                                if (pos < CAP) g_cand[rowBase + row][pos] = col;
                            }
                        }
                }
        }
    }
}

// ---------------------------------------------------------------------------
// Fused rescore + output: ONE WARP PER ROW.
// Fast path: cnt==1 means the sole candidate IS the argmax (screen guarantees
// the true argmax is among candidates) -> no dot, no reduce.
// Slow path: lane i rescoes candidate i with the sequential-order dot
// (per-thread order preserved); winner via 64-bit shuffle-max over packed
// keys (same max / first-index tie-break semantics as atomicMax).
// Then the warp gathers cn[idx] coalesced, writes zq, reduces loss partial.
// ---------------------------------------------------------------------------
__global__ __launch_bounds__(256) void finalize_rows(float* __restrict__ zq,
                                                     float* __restrict__ idx_out,
                                                     int do_loss) {
    const int lane = threadIdx.x & 31;
    const int n = (blockIdx.x * 256 + threadIdx.x) >> 5;   // one warp per row
    const float* zrow = g_zn + (size_t)n * D_DIM;
    const int cnt = g_candcnt[n];
    int idx;

    if (cnt == 1) {
        idx = g_cand[n][0];                 // singleton candidate is the argmax
    } else {
        unsigned long long best = 0ull;
        if (cnt <= CAP) {
            for (int i = lane; i < cnt; i += 32) {
                int col = g_cand[n][i];
                float s = dot_seq(zrow, g_cn + (size_t)col * D_DIM);
                unsigned long long k = pack_key(s, col);
                if (k > best) best = k;
            }
        } else {
            // overflow fallback (never expected): exact scan
            for (int col = lane; col < K_CODES; col += 32) {
                float s = dot_seq(zrow, g_cn + (size_t)col * D_DIM);
                unsigned long long k = pack_key(s, col);
                if (k > best) best = k;
            }
        }
        #pragma unroll
        for (int o = 16; o; o >>= 1) {
            unsigned long long other = __shfl_xor_sync(0xffffffffu, best, o);
            if (other > best) best = other;
        }
        idx = (int)(~(unsigned)best);
    }

    // gather cn[idx] -> zq (coalesced: lane + 32q float4s), loss partial
    const float4* crow = (const float4*)(g_cn + (size_t)idx * D_DIM);
    const float4* zrow4 = (const float4*)zrow;
    float4* orow = (float4*)(zq + (size_t)n * D_DIM);
    float ss = 0.0f;
    #pragma unroll
    for (int q = 0; q < 4; ++q) {
        float4 cv = crow[lane + q * 32];
        orow[lane + q * 32] = cv;
        if (do_loss) {
            float4 zv = zrow4[lane + q * 32];
            float dx = cv.x - zv.x, dy = cv.y - zv.y;
            float dz = cv.z - zv.z, dw = cv.w - zv.w;
            ss += dx * dx + dy * dy + dz * dz + dw * dw;
        }
    }
    if (idx_out && lane == 0) idx_out[n] = (float)idx;
    if (do_loss) {
        #pragma unroll
        for (int o = 16; o; o >>= 1) ss += __shfl_xor_sync(0xffffffffu, ss, o);
        if (lane == 0) atomicAdd(&g_loss, ss);
    }
}

__global__ void finalize_loss(float* __restrict__ loss_slot) {
    *loss_slot = 1.5f * g_loss / 16777216.0f;   // (beta+1) * mean, N*D = 2^24
}

// ---------------------------------------------------------------------------
extern "C" void kernel_launch(void* const* d_in, const int* in_sizes, int n_in,
                              void* d_out, int out_size) {
    const float* z = (const float*)d_in[0];
    const float* codebook = (const float*)d_in[1];
    float* out = (float*)d_out;

    const long long ND = (long long)N_ROWS * D_DIM;
    float* zq = out;
    float* idx_out   = (out_size >= ND + N_ROWS)     ? (out + ND) : nullptr;
    float* loss_slot = (out_size >= ND + N_ROWS + 1) ? (out + ND + N_ROWS) : nullptr;

    cudaFuncSetAttribute(gemm_screen,
                         cudaFuncAttributeMaxDynamicSharedMemorySize, SMEM_TOT);

    normalize_all<<<N_ROWS + K_CODES, 128>>>(z, codebook);
    gemm_screen<<<dim3(4, 256), 256, SMEM_TOT>>>();
    finalize_rows<<<N_ROWS / 8, 256>>>(zq, idx_out, loss_slot != nullptr);
    if (loss_slot) finalize_loss<<<1, 1>>>(loss_slot);
}

// round 14
// speedup vs baseline: 1.7301x; 1.7301x over previous
#include <cuda_runtime.h>
#include <cuda_bf16.h>
#include <cstdint>

#define N_ROWS  32768
#define D_DIM   512
#define K_CODES 8192
#define CAP     64
// Worst-case bf16 screening error bound: 2 * 2^-8 = 7.8e-3. EPS must exceed it.
#define EPS_MARGIN 1.25e-2f

// ---------------------------------------------------------------------------
// Device scratch
// ---------------------------------------------------------------------------
__device__ float          g_zn[N_ROWS  * D_DIM];   // 64 MB normalized z (fp32)
__device__ float          g_cn[K_CODES * D_DIM];   // 16 MB normalized codebook (fp32)
__device__ __nv_bfloat16  g_zb[N_ROWS  * D_DIM];   // 32 MB bf16 zn
__device__ __nv_bfloat16  g_cb[K_CODES * D_DIM];   //  8 MB bf16 cn
__device__ int            g_cand[N_ROWS][CAP];
__device__ int            g_candcnt[N_ROWS];
__device__ uint32_t       g_rowmax[N_ROWS];        // global running max (mono bits)
__device__ float          g_loss;

// ---------------------------------------------------------------------------
// Helpers
// ---------------------------------------------------------------------------
__device__ __forceinline__ uint32_t smem_u32(const void* p) {
    uint32_t a;
    asm("{ .reg .u64 t; cvta.to.shared.u64 t, %1; cvt.u32.u64 %0, t; }"
        : "=r"(a) : "l"(p));
    return a;
}
#define SWZ(o) ((o) ^ (((o) >> 3) & 0x70))

__device__ __forceinline__ void cp_async16(uint32_t dst, const void* src) {
    asm volatile("cp.async.cg.shared.global [%0], [%1], 16;"
                 :: "r"(dst), "l"(src) : "memory");
}
#define CP_COMMIT() asm volatile("cp.async.commit_group;" ::: "memory")
#define CP_WAIT1()  asm volatile("cp.async.wait_group 1;" ::: "memory")

__device__ __forceinline__ void ldsm_x4(uint32_t* r, uint32_t addr) {
    asm volatile("ldmatrix.sync.aligned.m8n8.x4.shared.b16 {%0,%1,%2,%3}, [%4];"
                 : "=r"(r[0]), "=r"(r[1]), "=r"(r[2]), "=r"(r[3]) : "r"(addr));
}
__device__ __forceinline__ void mma_bf16(float* c, const uint32_t* a,
                                         uint32_t b0, uint32_t b1) {
    asm volatile(
        "mma.sync.aligned.m16n8k16.row.col.f32.bf16.bf16.f32 "
        "{%0,%1,%2,%3}, {%4,%5,%6,%7}, {%8,%9}, {%0,%1,%2,%3};"
        : "+f"(c[0]), "+f"(c[1]), "+f"(c[2]), "+f"(c[3])
        : "r"(a[0]), "r"(a[1]), "r"(a[2]), "r"(a[3]), "r"(b0), "r"(b1));
}

// monotone float <-> uint (order-preserving)
__device__ __forceinline__ uint32_t mono(float v) {
    unsigned u = __float_as_uint(v);
    return (u & 0x80000000u) ? ~u : (u | 0x80000000u);
}
__device__ __forceinline__ float unmono(uint32_t u) {
    return __uint_as_float((u & 0x80000000u) ? (u & 0x7fffffffu) : ~u);
}
__device__ __forceinline__ unsigned long long pack_key(float v, int col) {
    return ((unsigned long long)mono(v) << 32) | (unsigned)(~col);
}

// Sequential-order exact fp32 dot (bit-identical to the R1 kernel order that
// matched the reference argmax on every row).
__device__ __forceinline__ float dot_seq(const float* __restrict__ a,
                                         const float* __restrict__ b) {
    float s = 0.0f;
    #pragma unroll 16
    for (int q = 0; q < D_DIM / 4; ++q) {
        float4 av = ((const float4*)a)[q];
        float4 bv = ((const float4*)b)[q];
        s = fmaf(av.x, bv.x, s);
        s = fmaf(av.y, bv.y, s);
        s = fmaf(av.z, bv.z, s);
        s = fmaf(av.w, bv.w, s);
    }
    return s;
}

// ---------------------------------------------------------------------------
// Row L2-normalize z -> fp32 + bf16; also init per-row screening state.
__global__ void normalize_z(const float* __restrict__ in) {
    int row = blockIdx.x;
    if (threadIdx.x == 0) {
        g_candcnt[row] = 0;
        g_rowmax[row] = 0u;                 // mono(-inf)
        if (row == 0) g_loss = 0.0f;
    }
    float4 v = ((const float4*)(in + (size_t)row * D_DIM))[threadIdx.x];
    float ss = v.x * v.x + v.y * v.y + v.z * v.z + v.w * v.w;
    #pragma unroll
    for (int o = 16; o; o >>= 1) ss += __shfl_xor_sync(0xffffffffu, ss, o);
    __shared__ float ws[4];
    if ((threadIdx.x & 31) == 0) ws[threadIdx.x >> 5] = ss;
    __syncthreads();
    float inv = 1.0f / fmaxf(sqrtf(ws[0] + ws[1] + ws[2] + ws[3]), 1e-12f);
    float4 o4 = make_float4(v.x * inv, v.y * inv, v.z * inv, v.w * inv);
    ((float4*)(g_zn + (size_t)row * D_DIM))[threadIdx.x] = o4;
    __nv_bfloat162 b0 = __floats2bfloat162_rn(o4.x, o4.y);
    __nv_bfloat162 b1 = __floats2bfloat162_rn(o4.z, o4.w);
    ((uint2*)(g_zb + (size_t)row * D_DIM))[threadIdx.x] =
        make_uint2(*(uint32_t*)&b0, *(uint32_t*)&b1);
}

// Row L2-normalize codebook -> fp32 + bf16.
__global__ void normalize_cb(const float* __restrict__ in) {
    int row = blockIdx.x;
    float4 v = ((const float4*)(in + (size_t)row * D_DIM))[threadIdx.x];
    float ss = v.x * v.x + v.y * v.y + v.z * v.z + v.w * v.w;
    #pragma unroll
    for (int o = 16; o; o >>= 1) ss += __shfl_xor_sync(0xffffffffu, ss, o);
    __shared__ float ws[4];
    if ((threadIdx.x & 31) == 0) ws[threadIdx.x >> 5] = ss;
    __syncthreads();
    float inv = 1.0f / fmaxf(sqrtf(ws[0] + ws[1] + ws[2] + ws[3]), 1e-12f);
    float4 o4 = make_float4(v.x * inv, v.y * inv, v.z * inv, v.w * inv);
    ((float4*)(g_cn + (size_t)row * D_DIM))[threadIdx.x] = o4;
    __nv_bfloat162 b0 = __floats2bfloat162_rn(o4.x, o4.y);
    __nv_bfloat162 b1 = __floats2bfloat162_rn(o4.z, o4.w);
    ((uint2*)(g_cb + (size_t)row * D_DIM))[threadIdx.x] =
        make_uint2(*(uint32_t*)&b0, *(uint32_t*)&b1);
}

// ---------------------------------------------------------------------------
// HMMA bf16 screening GEMM + prefix-max candidate collection.
// Grid (4, 256): blockIdx.y = 128-row tile, blockIdx.x = 2048-col quarter.
// ---------------------------------------------------------------------------
#define SMEM_A    0           // 8 chunks * 16384 = 131072
#define SMEM_B    131072      // 3 stages * 32768 = 98304
#define SMEM_RMAX 229376      // 128 * 4 = 512
#define SMEM_TOT  229888

__device__ __forceinline__ void prefetch_b(uint32_t sb, int colQ, int cg, int tid) {
    const int nt = cg >> 3, c = cg & 7;
    const uint32_t dstb = sb + SMEM_B + (cg % 3) * 32768;
    #pragma unroll
    for (int it = 0; it < 8; ++it) {
        int u = tid + it * 256;             // 0..2047 16B units
        int r = u >> 3, cu = u & 7;         // code row 0..255
        cp_async16(dstb + SWZ(r * 128 + cu * 16),
                   &g_cb[(size_t)(colQ + nt * 256 + r) * D_DIM + c * 64 + cu * 8]);
    }
}

__global__ __launch_bounds__(256, 1) void gemm_screen() {
    extern __shared__ char smem[];
    const uint32_t sb = smem_u32(smem);
    const int tid = threadIdx.x;
    const int lane = tid & 31;
    const int wid = tid >> 5;
    const int warpM = wid >> 2;      // 0..1  (64 rows each)
    const int warpN = wid & 3;       // 0..3  (64 cols each)
    const int rowBase = blockIdx.y * 128;
    const int colQ = blockIdx.x * 2048;
    uint32_t* srunmax = (uint32_t*)(smem + SMEM_RMAX);

    if (tid < 128) srunmax[tid] = 0u;   // mono(-inf)

    // Group 0: resident A (128 rows x 512 bf16, chunk-major, swizzled)
    #pragma unroll
    for (int it = 0; it < 32; ++it) {
        int u = tid + it * 256;             // 0..8191 16B-units
        int c  = u >> 10;
        int r  = (u >> 3) & 127;
        int cu = u & 7;
        cp_async16(sb + SMEM_A + c * 16384 + SWZ(r * 128 + cu * 16),
                   &g_zb[(size_t)(rowBase + r) * D_DIM + c * 64 + cu * 8]);
    }
    CP_COMMIT();

    prefetch_b(sb, colQ, 0, tid); CP_COMMIT();
    prefetch_b(sb, colQ, 1, tid); CP_COMMIT();

    float acc[4][8][4];                 // 64 rows x 64 cols per warp

    const int ra = warpM * 64 + (lane & 15);
    const int ca = (lane >> 4);
    const int nb = warpN * 64 + (lane & 7) + ((lane >> 4) << 3);
    const int cb = (lane >> 3) & 1;

    for (int cg = 0; cg < 64; ++cg) {   // 8 tiles * 8 chunks
        const int nt = cg >> 3;
        const int c  = cg & 7;

        CP_WAIT1();
        __syncthreads();
        // safe: slot (cg+2)%3 == (cg-1)%3; barrier above post-dates chunk
        // cg-1 compute on all warps.
        if (cg + 2 < 64) prefetch_b(sb, colQ, cg + 2, tid);
        CP_COMMIT();

        if (c == 0) {
            #pragma unroll
            for (int m = 0; m < 4; ++m)
                #pragma unroll
                for (int j = 0; j < 8; ++j)
                    #pragma unroll
                    for (int e = 0; e < 4; ++e) acc[m][j][e] = 0.0f;
        }

        const uint32_t Ab = sb + SMEM_A + c * 16384;
        const uint32_t Bb = sb + SMEM_B + (cg % 3) * 32768;

        #pragma unroll
        for (int s = 0; s < 4; ++s) {   // 4 k16-steps within the 64-k chunk
            uint32_t a[4][4], b4[4][4];
            #pragma unroll
            for (int m = 0; m < 4; ++m)
                ldsm_x4(a[m], Ab + SWZ((ra + m * 16) * 128 + (s * 2 + ca) * 16));
            #pragma unroll
            for (int q = 0; q < 4; ++q)
                ldsm_x4(b4[q], Bb + SWZ((nb + q * 16) * 128 + (s * 2 + cb) * 16));
            #pragma unroll
            for (int m = 0; m < 4; ++m)
                #pragma unroll
                for (int j = 0; j < 8; ++j)
                    mma_bf16(acc[m][j], a[m],
                             b4[j >> 1][(j & 1) * 2], b4[j >> 1][(j & 1) * 2 + 1]);
        }

        if (c == 7) {
            // ---- epilogue for tile nt ----
            const int g = lane >> 2, tg = lane & 3;
            #pragma unroll
            for (int m = 0; m < 4; ++m)
                #pragma unroll
                for (int h = 0; h < 2; ++h) {
                    int row = warpM * 64 + m * 16 + h * 8 + g;
                    float mx = -1e30f;
                    #pragma unroll
                    for (int j = 0; j < 8; ++j)
                        mx = fmaxf(mx, fmaxf(acc[m][j][h * 2], acc[m][j][h * 2 + 1]));
                    mx = fmaxf(mx, __shfl_xor_sync(0xffffffffu, mx, 1));
                    mx = fmaxf(mx, __shfl_xor_sync(0xffffffffu, mx, 2));
                    if (tg == 0) atomicMax(&srunmax[row], mono(mx));
                }
            __syncthreads();
            // couple with global running max (publish ours, adopt best known)
            if (tid < 128) {
                uint32_t lm = srunmax[tid];
                uint32_t old = atomicMax(&g_rowmax[rowBase + tid], lm);
                if (old > lm) srunmax[tid] = old;
            }
            __syncthreads();
            #pragma unroll
            for (int m = 0; m < 4; ++m)
                #pragma unroll
                for (int h = 0; h < 2; ++h) {
                    int row = warpM * 64 + m * 16 + h * 8 + g;
                    float thr = unmono(srunmax[row]) - EPS_MARGIN;
                    #pragma unroll
                    for (int j = 0; j < 8; ++j)
                        #pragma unroll
                        for (int e = 0; e < 2; ++e) {
                            float v = acc[m][j][h * 2 + e];
                            if (v >= thr) {
                                int col = colQ + nt * 256 + warpN * 64 + j * 8 + 2 * tg + e;
                                int pos = atomicAdd(&g_candcnt[rowBase + row], 1);
                                if (pos < CAP) g_cand[rowBase + row][pos] = col;
                            }
                        }
                }
        }
    }
}

// ---------------------------------------------------------------------------
// Fused rescore + output: ONE WARP PER ROW.
// Fast path: cnt==1 -> the sole candidate IS the argmax (the true argmax is
// always emitted: its approx sim >= truemax - delta >= thr for EPS >= 2*delta).
// Slow path: lane i rescoes candidate i with the sequential-order dot
// (per-thread order preserved); winner via 64-bit shuffle-max over packed
// keys (same max / first-index tie-break semantics as atomicMax).
// Then the warp gathers cn[idx] coalesced, writes zq, reduces loss partial.
// ---------------------------------------------------------------------------
__global__ __launch_bounds__(256) void finalize_rows(float* __restrict__ zq,
                                                     float* __restrict__ idx_out,
                                                     int do_loss) {
    const int lane = threadIdx.x & 31;
    const int n = (blockIdx.x * 256 + threadIdx.x) >> 5;   // one warp per row
    const float* zrow = g_zn + (size_t)n * D_DIM;
    const int cnt = g_candcnt[n];
    int idx;

    if (cnt == 1) {
        idx = g_cand[n][0];                 // singleton candidate is the argmax
    } else {
        unsigned long long best = 0ull;
        if (cnt <= CAP) {
            for (int i = lane; i < cnt; i += 32) {
                int col = g_cand[n][i];
                float s = dot_seq(zrow, g_cn + (size_t)col * D_DIM);
                unsigned long long k = pack_key(s, col);
                if (k > best) best = k;
            }
        } else {
            // overflow fallback (never expected): exact scan
            for (int col = lane; col < K_CODES; col += 32) {
                float s = dot_seq(zrow, g_cn + (size_t)col * D_DIM);
                unsigned long long k = pack_key(s, col);
                if (k > best) best = k;
            }
        }
        #pragma unroll
        for (int o = 16; o; o >>= 1) {
            unsigned long long other = __shfl_xor_sync(0xffffffffu, best, o);
            if (other > best) best = other;
        }
        idx = (int)(~(unsigned)best);
    }

    // gather cn[idx] -> zq (coalesced: lane + 32q float4s), loss partial
    const float4* crow = (const float4*)(g_cn + (size_t)idx * D_DIM);
    const float4* zrow4 = (const float4*)zrow;
    float4* orow = (float4*)(zq + (size_t)n * D_DIM);
    float ss = 0.0f;
    #pragma unroll
    for (int q = 0; q < 4; ++q) {
        float4 cv = crow[lane + q * 32];
        orow[lane + q * 32] = cv;
        if (do_loss) {
            float4 zv = zrow4[lane + q * 32];
            float dx = cv.x - zv.x, dy = cv.y - zv.y;
            float dz = cv.z - zv.z, dw = cv.w - zv.w;
            ss += dx * dx + dy * dy + dz * dz + dw * dw;
        }
    }
    if (idx_out && lane == 0) idx_out[n] = (float)idx;
    if (do_loss) {
        #pragma unroll
        for (int o = 16; o; o >>= 1) ss += __shfl_xor_sync(0xffffffffu, ss, o);
        if (lane == 0) atomicAdd(&g_loss, ss);
    }
}

__global__ void finalize_loss(float* __restrict__ loss_slot) {
    *loss_slot = 1.5f * g_loss / 16777216.0f;   // (beta+1) * mean, N*D = 2^24
}

// ---------------------------------------------------------------------------
extern "C" void kernel_launch(void* const* d_in, const int* in_sizes, int n_in,
                              void* d_out, int out_size) {
    const float* z = (const float*)d_in[0];
    const float* codebook = (const float*)d_in[1];
    float* out = (float*)d_out;

    const long long ND = (long long)N_ROWS * D_DIM;
    float* zq = out;
    float* idx_out   = (out_size >= ND + N_ROWS)     ? (out + ND) : nullptr;
    float* loss_slot = (out_size >= ND + N_ROWS + 1) ? (out + ND + N_ROWS) : nullptr;

    cudaFuncSetAttribute(gemm_screen,
                         cudaFuncAttributeMaxDynamicSharedMemorySize, SMEM_TOT);

    normalize_z<<<N_ROWS, 128>>>(z);
    normalize_cb<<<K_CODES, 128>>>(codebook);
    gemm_screen<<<dim3(4, 256), 256, SMEM_TOT>>>();
    finalize_rows<<<N_ROWS / 8, 256>>>(zq, idx_out, loss_slot != nullptr);
    if (loss_slot) finalize_loss<<<1, 1>>>(loss_slot);
}